// round 9
// baseline (speedup 1.0000x reference)
#include <cuda_runtime.h>
#include <cuda_bf16.h>
#include <cstdint>

#define BATCH 512
#define TLEN  512
#define IDIM  128
#define HDIM  512
#define NCTA  256
#define NTHR  256

#define OFF_BSUM  0
#define OFF_XCH   1024                    // 4 m * 2 halves * 2304B = 18432
#define OFF_WH    19456                   // 40960
#define OFF_WL    (OFF_WH + 40960)        // 60416
#define SMEM_BYTES (OFF_WL + 40960)       // 101376

// x and h pre-split bf16 hi/lo, fragment-permuted word layout:
// per 8-word group, logical word d (0..7) stored at slot 2*(d&3) + (d>>2)
__device__ uint32_t g_xhi[BATCH * TLEN * IDIM / 2];
__device__ uint32_t g_xlo[BATCH * TLEN * IDIM / 2];
__device__ uint32_t g_hhi[2][BATCH * HDIM / 2];
__device__ uint32_t g_hlo[2][BATCH * HDIM / 2];
__device__ unsigned g_count, g_gen;

__device__ __forceinline__ uint32_t smem_u32(const void* p) {
    uint32_t a;
    asm("{ .reg .u64 t; cvta.to.shared.u64 t, %1; cvt.u32.u64 %0, t; }" : "=r"(a) : "l"(p));
    return a;
}
#define SWZ(o) ((o) ^ (((o) >> 3) & 0x70))

__device__ __forceinline__ void ldm4(uint32_t* r, uint32_t addr) {
    asm volatile("ldmatrix.sync.aligned.m8n8.x4.shared.b16 {%0,%1,%2,%3}, [%4];"
        : "=r"(r[0]), "=r"(r[1]), "=r"(r[2]), "=r"(r[3]) : "r"(addr));
}
__device__ __forceinline__ void mma16816(float* d, const uint32_t* a, const uint32_t* b) {
    asm volatile("mma.sync.aligned.m16n8k16.row.col.f32.bf16.bf16.f32 "
        "{%0,%1,%2,%3},{%4,%5,%6,%7},{%8,%9},{%0,%1,%2,%3};"
        : "+f"(d[0]), "+f"(d[1]), "+f"(d[2]), "+f"(d[3])
        : "r"(a[0]), "r"(a[1]), "r"(a[2]), "r"(a[3]), "r"(b[0]), "r"(b[1]));
}
__device__ __forceinline__ uint32_t ldcg_u32(const uint32_t* p) {
    uint32_t v;
    asm volatile("ld.global.cg.b32 %0, [%1];" : "=r"(v) : "l"(p));
    return v;
}
__device__ __forceinline__ uint2 ldcg_u2(const uint32_t* p) {
    uint2 v;
    asm volatile("ld.global.cg.v2.b32 {%0,%1}, [%2];" : "=r"(v.x), "=r"(v.y) : "l"(p));
    return v;
}

// ---- grid barrier: acq_rel arrival + release/acquire generation ----
__device__ __forceinline__ void gb_arrive(int tid, unsigned target) {
    if (tid == 0) {
        unsigned old;
        asm volatile("atom.acq_rel.gpu.global.add.u32 %0, [%1], 1;"
                     : "=r"(old) : "l"(&g_count) : "memory");
        if (old == NCTA - 1) {
            asm volatile("st.relaxed.gpu.global.u32 [%0], %1;" :: "l"(&g_count), "r"(0u) : "memory");
            asm volatile("st.release.gpu.global.u32 [%0], %1;" :: "l"(&g_gen), "r"(target) : "memory");
        }
    }
}
__device__ __forceinline__ void gb_wait(int tid, unsigned target) {
    if (tid == 0) {
        unsigned g;
        do {
            asm volatile("ld.acquire.gpu.global.u32 %0, [%1];" : "=r"(g) : "l"(&g_gen) : "memory");
        } while ((int)(g - target) < 0);
    }
    __syncthreads();
}

__device__ __forceinline__ void split4(float4 v, uint32_t* hi, uint32_t* lo) {
    __nv_bfloat162 h0 = __floats2bfloat162_rn(v.x, v.y);
    __nv_bfloat162 h1 = __floats2bfloat162_rn(v.z, v.w);
    __nv_bfloat162 l0 = __floats2bfloat162_rn(v.x - __bfloat162float(h0.x),
                                              v.y - __bfloat162float(h0.y));
    __nv_bfloat162 l1 = __floats2bfloat162_rn(v.z - __bfloat162float(h1.x),
                                              v.w - __bfloat162float(h1.y));
    hi[0] = *(uint32_t*)&h0; hi[1] = *(uint32_t*)&h1;
    lo[0] = *(uint32_t*)&l0; lo[1] = *(uint32_t*)&l1;
}
__device__ __forceinline__ void cvt_sts(float4 v, uint32_t ah, uint32_t al) {
    uint32_t hw[2], lw[2];
    split4(v, hw, lw);
    uint64_t hv = ((uint64_t)hw[1] << 32) | hw[0];
    uint64_t lv = ((uint64_t)lw[1] << 32) | lw[0];
    asm volatile("st.shared.b64 [%0], %1;" :: "r"(ah), "l"(hv) : "memory");
    asm volatile("st.shared.b64 [%0], %1;" :: "r"(al), "l"(lv) : "memory");
}

__device__ __forceinline__ float sig_(float x) { return 1.0f / (1.0f + __expf(-x)); }
__device__ __forceinline__ float tnh_(float x) { return 2.0f / (1.0f + __expf(-2.0f * x)) - 1.0f; }

__global__ void __launch_bounds__(NTHR, 2) lstm_mma5(
    const float* __restrict__ x,
    const float* __restrict__ eWih, const float* __restrict__ eWhh,
    const float* __restrict__ ebih, const float* __restrict__ ebhh,
    const float* __restrict__ dWih, const float* __restrict__ dWhh,
    const float* __restrict__ dbih, const float* __restrict__ dbhh,
    const float* __restrict__ fcW,  const float* __restrict__ fcb,
    float* __restrict__ out)
{
    extern __shared__ __align__(1024) char smem[];
    const uint32_t sb = smem_u32(smem);
    const int tid = threadIdx.x, wid = tid >> 5, lane = tid & 31;
    const int m  = wid >> 1;            // m-tile: rows 32m..32m+31
    const int kp = wid & 1;             // split-K parity: ks = kp + 2*ki
    const int bx = blockIdx.x;          // 64 h-slices (8 cols each)
    const int jb = bx * 8;
    const int b0 = blockIdx.y * 128;    // batch base (4 groups)
    const int lq = lane >> 2;           // 0..7
    const int lr = (lane & 3) << 1;     // 0,2,4,6
    const int cid = blockIdx.y * 64 + bx;

    float* bsum = (float*)(smem + OFF_BSUM);

    unsigned gbase = 0;
    if (tid == 0) gbase = *(volatile unsigned*)&g_gen;

    // ---- prologue: zero h0 slice; convert x to permuted bf16 hi/lo ----
    for (int i = tid; i < 512; i += NTHR) {
        size_t wi = (size_t)(b0 + (i >> 2)) * 256 + (size_t)bx * 4 + (i & 3);
        g_hhi[0][wi] = 0u; g_hlo[0][wi] = 0u;
    }
    for (size_t j = (size_t)cid * NTHR + tid; j < (size_t)BATCH * TLEN * IDIM / 4;
         j += (size_t)NCTA * NTHR) {
        float4 v = *(const float4*)(x + 4 * j);
        uint32_t hw[2], lw[2];
        split4(v, hw, lw);
        #pragma unroll
        for (int k = 0; k < 2; ++k) {
            size_t P = 2 * j + k;
            uint32_t w = (uint32_t)(P & 63);
            uint32_t d = w & 7;
            uint32_t slot = 2u * (d & 3) + (d >> 2);
            size_t widx = (P & ~(size_t)63) + (w & 32) + (((w >> 3) & 3) << 3) + slot;
            g_xhi[widx] = hw[k];
            g_xlo[widx] = lw[k];
        }
    }

    float cst[4];
    #pragma unroll
    for (int j = 0; j < 4; ++j) cst[j] = 0.0f;

    gb_arrive(tid, gbase + 1);

    uint32_t bufA[16], bufB[16], lob[16];

    #pragma unroll 1
    for (int s = 0; s < 2 * TLEN; ++s) {
        const int dec = (s >= TLEN) ? 1 : 0;
        const int t = dec ? s - TLEN : s;
        const uint32_t* hhi = g_hhi[s & 1];
        const uint32_t* hlo = g_hlo[s & 1];

        // ---- per-phase weight + bias preload (hi/lo bf16, SW128) ----
        if (s == 0 || s == TLEN) {
            const float* Wih = dec ? dWih : eWih;
            const float* Whh = dec ? dWhh : eWhh;
            const float* bi  = dec ? dbih : ebih;
            const float* bh_ = dec ? dbhh : ebhh;
            #pragma unroll 1
            for (int i = tid; i < 5120; i += NTHR) {   // 32 rows x 160 float4
                int rl = i / 160, k4 = i % 160;
                int c = k4 >> 4, kin = k4 & 15;
                int grow = (rl >> 3) * HDIM + jb + (rl & 7);
                const float* sp = (c < 2) ? (Wih + (size_t)grow * IDIM + c * 64 + kin * 4)
                                          : (Whh + (size_t)grow * HDIM + (c - 2) * 64 + kin * 4);
                float4 v = *(const float4*)sp;
                uint32_t off = (uint32_t)c * 4096u + SWZ((uint32_t)rl * 128u + (uint32_t)kin * 8u);
                cvt_sts(v, sb + OFF_WH + off, sb + OFF_WL + off);
            }
            if (tid < 32) {
                int g = tid >> 3, j = tid & 7;
                bsum[tid] = bi[g * HDIM + jb + j] + bh_[g * HDIM + jb + j];
            }
            __syncthreads();
        }

        float acc[2][4][4];
        #pragma unroll
        for (int fi = 0; fi < 2; ++fi)
            #pragma unroll
            for (int nt = 0; nt < 4; ++nt)
                #pragma unroll
                for (int q = 0; q < 4; ++q) acc[fi][nt][q] = 0.0f;

        auto pf_hi = [&](int c, uint32_t* buf) {
            #pragma unroll
            for (int ki = 0; ki < 2; ++ki) {
                const int ks = kp + 2 * ki;
                #pragma unroll
                for (int fi = 0; fi < 2; ++fi)
                    #pragma unroll
                    for (int rq = 0; rq < 2; ++rq) {
                        const int r = b0 + 32 * m + fi * 16 + lq + 8 * rq;
                        uint2 v;
                        if (c < 2)
                            v = ldcg_u2(g_xhi + ((size_t)r * TLEN + t) * 64
                                              + (size_t)(c * 32 + ks * 8 + lr));
                        else
                            v = ldcg_u2(hhi + (size_t)r * 256
                                            + (size_t)((c - 2) * 32 + ks * 8 + lr));
                        buf[ki * 8 + fi * 4 + rq]     = v.x;
                        buf[ki * 8 + fi * 4 + 2 + rq] = v.y;
                    }
            }
        };
        auto pf_lo = [&](int c, uint32_t* buf) {
            #pragma unroll
            for (int ki = 0; ki < 2; ++ki) {
                const int ks = kp + 2 * ki;
                #pragma unroll
                for (int fi = 0; fi < 2; ++fi)
                    #pragma unroll
                    for (int rq = 0; rq < 2; ++rq) {
                        const int r = b0 + 32 * m + fi * 16 + lq + 8 * rq;
                        uint2 v;
                        if (c < 2)
                            v = ldcg_u2(g_xlo + ((size_t)r * TLEN + t) * 64
                                              + (size_t)(c * 32 + ks * 8 + lr));
                        else
                            v = ldcg_u2(hlo + (size_t)r * 256
                                            + (size_t)((c - 2) * 32 + ks * 8 + lr));
                        buf[ki * 8 + fi * 4 + rq]     = v.x;
                        buf[ki * 8 + fi * 4 + 2 + rq] = v.y;
                    }
            }
        };
        auto body = [&](int c, const uint32_t* hib, const uint32_t* lo) {
            const uint32_t wb  = sb + OFF_WH + (uint32_t)c * 4096u;
            const uint32_t rbs = (uint32_t)(((lane & 16) ? 8 : 0) + (lane & 7));
            #pragma unroll
            for (int ki = 0; ki < 2; ++ki) {
                const int ks = kp + 2 * ki;
                const uint32_t kc = (uint32_t)(ks * 32 + ((lane & 8) ? 16 : 0));
                #pragma unroll
                for (int pp = 0; pp < 2; ++pp) {
                    uint32_t bhf[4], blf[4];
                    uint32_t boff = SWZ(((uint32_t)(pp * 16) + rbs) * 128u + kc);
                    ldm4(bhf, wb + boff);
                    ldm4(blf, wb + 40960u + boff);
                    #pragma unroll
                    for (int fi = 0; fi < 2; ++fi)
                        #pragma unroll
                        for (int ntl = 0; ntl < 2; ++ntl)
                            mma16816(acc[fi][pp * 2 + ntl], hib + ki * 8 + fi * 4, bhf + 2 * ntl);
                    #pragma unroll
                    for (int fi = 0; fi < 2; ++fi)
                        #pragma unroll
                        for (int ntl = 0; ntl < 2; ++ntl)
                            mma16816(acc[fi][pp * 2 + ntl], hib + ki * 8 + fi * 4, blf + 2 * ntl);
                    #pragma unroll
                    for (int fi = 0; fi < 2; ++fi)
                        #pragma unroll
                        for (int ntl = 0; ntl < 2; ++ntl)
                            mma16816(acc[fi][pp * 2 + ntl], lo + ki * 8 + fi * 4, bhf + 2 * ntl);
                }
            }
        };

        // x-chunks (h-independent) before the barrier wait
        pf_hi(0, bufA); pf_lo(0, lob); pf_hi(1, bufB);
        body(0, bufA, lob);
        pf_lo(1, lob);
        body(1, bufB, lob);
        gb_wait(tid, gbase + 1 + (unsigned)s);
        pf_hi(2, bufA);
        #pragma unroll 1
        for (int c = 2; c < 10; ++c) {
            uint32_t* cur = (c & 1) ? bufB : bufA;
            uint32_t* nxt = (c & 1) ? bufA : bufB;
            pf_lo(c, lob);
            if (c < 9) pf_hi(c + 1, nxt);
            body(c, cur, lob);
        }

        // ---- single-round bidirectional split-K exchange ----
        // warp kp stores its acc[1-kp] half; reads pair's half into acc[kp]
        const uint32_t myslot = sb + OFF_XCH + (uint32_t)m * 4608u + (uint32_t)kp * 2304u;
        const uint32_t othslot = sb + OFF_XCH + (uint32_t)m * 4608u + (uint32_t)(1 - kp) * 2304u;
        {
            const int fiS = 1 - kp;
            #pragma unroll
            for (int nt = 0; nt < 4; ++nt)
                #pragma unroll
                for (int qr = 0; qr < 2; ++qr) {
                    uint32_t a = myslot + (uint32_t)(lq + 8 * qr) * 144u
                                        + (uint32_t)(nt * 8 + lr) * 4u;
                    asm volatile("st.shared.v2.f32 [%0], {%1,%2};" :: "r"(a),
                        "f"(acc[fiS][nt][2 * qr]), "f"(acc[fiS][nt][2 * qr + 1]) : "memory");
                }
        }
        __syncthreads();
        {
            #pragma unroll
            for (int nt = 0; nt < 4; ++nt)
                #pragma unroll
                for (int qr = 0; qr < 2; ++qr) {
                    uint32_t a = othslot + (uint32_t)(lq + 8 * qr) * 144u
                                         + (uint32_t)(nt * 8 + lr) * 4u;
                    float px, py;
                    asm volatile("ld.shared.v2.f32 {%0,%1}, [%2];" : "=f"(px), "=f"(py) : "r"(a));
                    acc[kp][nt][2 * qr]     += px;
                    acc[kp][nt][2 * qr + 1] += py;
                }
        }

        // ---- fused gate epilogue: warp kp owns rows 32m + kp*16 + ... ----
        {
            const int nb = (s + 1) & 1;
            #pragma unroll
            for (int qr = 0; qr < 2; ++qr) {
                const int rloc = 32 * m + kp * 16 + lq + 8 * qr;
                float hv[2];
                #pragma unroll
                for (int e = 0; e < 2; ++e) {
                    const int q = 2 * qr + e, j = lr + e;
                    float pi  = acc[kp][0][q] + bsum[j];
                    float pf_ = acc[kp][1][q] + bsum[8 + j];
                    float pg  = acc[kp][2][q] + bsum[16 + j];
                    float po  = acc[kp][3][q] + bsum[24 + j];
                    float iv = sig_(pi), fv = sig_(pf_), gv = tnh_(pg), ov = sig_(po);
                    const int ci = qr * 2 + e;
                    float cn = fv * cst[ci] + iv * gv;
                    cst[ci] = cn;
                    hv[e] = ov * tnh_(cn);
                }
                __nv_bfloat162 h2 = __floats2bfloat162_rn(hv[0], hv[1]);
                __nv_bfloat162 l2 = __floats2bfloat162_rn(hv[0] - __bfloat162float(h2.x),
                                                          hv[1] - __bfloat162float(h2.y));
                const uint32_t slot = (uint32_t)(lr + (bx & 1));
                const size_t wi = (size_t)(b0 + rloc) * 256 + (size_t)(bx >> 1) * 8 + slot;
                g_hhi[nb][wi] = *(uint32_t*)&h2;
                g_hlo[nb][wi] = *(uint32_t*)&l2;
            }
        }
        __syncthreads();
        gb_arrive(tid, gbase + 2 + (unsigned)s);
    }

    // ---- fc epilogue: final h in buffer 0 (permuted layout) ----
    gb_wait(tid, gbase + 1 + 2 * TLEN);
    if (bx == 0) {
        for (int r = wid; r < 128; r += 8) {
            const size_t base = (size_t)(b0 + r) * 256;
            float ssum = 0.0f;
            for (int kk = lane; kk < 256; kk += 32) {
                uint32_t hwv = ldcg_u32(&g_hhi[0][base + kk]);
                uint32_t lwv = ldcg_u32(&g_hlo[0][base + kk]);
                int slot = kk & 7;
                int d = (slot & 1) * 4 + (slot >> 1);
                int J = (kk >> 5) * 64 + (((kk >> 3) & 3) * 8 + d) * 2;
                __nv_bfloat162 h2 = *(__nv_bfloat162*)&hwv;
                __nv_bfloat162 l2 = *(__nv_bfloat162*)&lwv;
                ssum += (__bfloat162float(h2.x) + __bfloat162float(l2.x)) * fcW[J]
                      + (__bfloat162float(h2.y) + __bfloat162float(l2.y)) * fcW[J + 1];
            }
            #pragma unroll
            for (int o = 16; o; o >>= 1) ssum += __shfl_xor_sync(0xffffffffu, ssum, o);
            if (lane == 0) out[b0 + r] = ssum + fcb[0];
        }
    }
}

extern "C" void kernel_launch(void* const* d_in, const int* in_sizes, int n_in,
                              void* d_out, int out_size)
{
    (void)in_sizes; (void)n_in; (void)out_size;
    cudaFuncSetAttribute(lstm_mma5, cudaFuncAttributeMaxDynamicSharedMemorySize, SMEM_BYTES);
    dim3 grid(64, 4);   // 64 h-slices x 4 batch groups = 256 CTAs (2/SM)
    lstm_mma5<<<grid, NTHR, SMEM_BYTES>>>(
        (const float*)d_in[0],
        (const float*)d_in[1], (const float*)d_in[2],
        (const float*)d_in[3], (const float*)d_in[4],
        (const float*)d_in[5], (const float*)d_in[6],
        (const float*)d_in[7], (const float*)d_in[8],
        (const float*)d_in[9], (const float*)d_in[10],
        (float*)d_out);
}

// round 10
// speedup vs baseline: 1.1589x; 1.1589x over previous
#include <cuda_runtime.h>
#include <cuda_bf16.h>
#include <cstdint>

#define BATCH 512
#define TLEN  512
#define IDIM  128
#define HDIM  512
#define NCTA  128
#define NTHR  256

#define OFF_BSUM  0
#define OFF_XCH   1024                    // 4 p * 2 halves * 4608B = 36864
#define OFF_WH    37888                   // 81920
#define OFF_WL    (OFF_WH + 81920)        // 119808
#define SMEM_BYTES (OFF_WL + 81920)       // 201728

// x and h pre-split bf16 hi/lo, fragment-permuted word layout:
// within each aligned 8-word group, logical word d (0..7) is stored at
// slot 2*(d&3) + (d>>2)  => lane fragment (d, d+4) is one adjacent pair.
__device__ uint32_t g_xhi[BATCH * TLEN * IDIM / 2];
__device__ uint32_t g_xlo[BATCH * TLEN * IDIM / 2];
__device__ uint32_t g_hhi[2][BATCH * HDIM / 2];
__device__ uint32_t g_hlo[2][BATCH * HDIM / 2];
__device__ unsigned g_count, g_gen;

__device__ __forceinline__ uint32_t smem_u32(const void* p) {
    uint32_t a;
    asm("{ .reg .u64 t; cvta.to.shared.u64 t, %1; cvt.u32.u64 %0, t; }" : "=r"(a) : "l"(p));
    return a;
}
#define SWZ(o) ((o) ^ (((o) >> 3) & 0x70))

__device__ __forceinline__ void ldm4(uint32_t* r, uint32_t addr) {
    asm volatile("ldmatrix.sync.aligned.m8n8.x4.shared.b16 {%0,%1,%2,%3}, [%4];"
        : "=r"(r[0]), "=r"(r[1]), "=r"(r[2]), "=r"(r[3]) : "r"(addr));
}
__device__ __forceinline__ void mma16816(float* d, const uint32_t* a, const uint32_t* b) {
    asm volatile("mma.sync.aligned.m16n8k16.row.col.f32.bf16.bf16.f32 "
        "{%0,%1,%2,%3},{%4,%5,%6,%7},{%8,%9},{%0,%1,%2,%3};"
        : "+f"(d[0]), "+f"(d[1]), "+f"(d[2]), "+f"(d[3])
        : "r"(a[0]), "r"(a[1]), "r"(a[2]), "r"(a[3]), "r"(b[0]), "r"(b[1]));
}
__device__ __forceinline__ uint32_t ldcg_u32(const uint32_t* p) {
    uint32_t v;
    asm volatile("ld.global.cg.b32 %0, [%1];" : "=r"(v) : "l"(p));
    return v;
}
__device__ __forceinline__ uint2 ldcg_u2(const uint32_t* p) {
    uint2 v;
    asm volatile("ld.global.cg.v2.b32 {%0,%1}, [%2];" : "=r"(v.x), "=r"(v.y) : "l"(p));
    return v;
}

// ---- grid barrier: acq_rel arrival + release/acquire generation ----
__device__ __forceinline__ void gb_arrive(int tid, unsigned target) {
    if (tid == 0) {
        unsigned old;
        asm volatile("atom.acq_rel.gpu.global.add.u32 %0, [%1], 1;"
                     : "=r"(old) : "l"(&g_count) : "memory");
        if (old == NCTA - 1) {
            asm volatile("st.relaxed.gpu.global.u32 [%0], %1;" :: "l"(&g_count), "r"(0u) : "memory");
            asm volatile("st.release.gpu.global.u32 [%0], %1;" :: "l"(&g_gen), "r"(target) : "memory");
        }
    }
}
__device__ __forceinline__ void gb_wait(int tid, unsigned target) {
    if (tid == 0) {
        unsigned g;
        do {
            asm volatile("ld.acquire.gpu.global.u32 %0, [%1];" : "=r"(g) : "l"(&g_gen) : "memory");
        } while ((int)(g - target) < 0);
    }
    __syncthreads();
}

__device__ __forceinline__ void split4(float4 v, uint32_t* hi, uint32_t* lo) {
    __nv_bfloat162 h0 = __floats2bfloat162_rn(v.x, v.y);
    __nv_bfloat162 h1 = __floats2bfloat162_rn(v.z, v.w);
    __nv_bfloat162 l0 = __floats2bfloat162_rn(v.x - __bfloat162float(h0.x),
                                              v.y - __bfloat162float(h0.y));
    __nv_bfloat162 l1 = __floats2bfloat162_rn(v.z - __bfloat162float(h1.x),
                                              v.w - __bfloat162float(h1.y));
    hi[0] = *(uint32_t*)&h0; hi[1] = *(uint32_t*)&h1;
    lo[0] = *(uint32_t*)&l0; lo[1] = *(uint32_t*)&l1;
}
__device__ __forceinline__ void cvt_sts(float4 v, uint32_t ah, uint32_t al) {
    uint32_t hw[2], lw[2];
    split4(v, hw, lw);
    uint64_t hv = ((uint64_t)hw[1] << 32) | hw[0];
    uint64_t lv = ((uint64_t)lw[1] << 32) | lw[0];
    asm volatile("st.shared.b64 [%0], %1;" :: "r"(ah), "l"(hv) : "memory");
    asm volatile("st.shared.b64 [%0], %1;" :: "r"(al), "l"(lv) : "memory");
}

__device__ __forceinline__ float sig_(float x) { return 1.0f / (1.0f + __expf(-x)); }
__device__ __forceinline__ float tnh_(float x) { return 2.0f / (1.0f + __expf(-2.0f * x)) - 1.0f; }

__global__ void __launch_bounds__(NTHR, 1) lstm_mma6(
    const float* __restrict__ x,
    const float* __restrict__ eWih, const float* __restrict__ eWhh,
    const float* __restrict__ ebih, const float* __restrict__ ebhh,
    const float* __restrict__ dWih, const float* __restrict__ dWhh,
    const float* __restrict__ dbih, const float* __restrict__ dbhh,
    const float* __restrict__ fcW,  const float* __restrict__ fcb,
    float* __restrict__ out)
{
    extern __shared__ __align__(1024) char smem[];
    const uint32_t sb = smem_u32(smem);
    const int tid = threadIdx.x, wid = tid >> 5, lane = tid & 31;
    const int p  = wid >> 1;            // m-tile: rows 32p..32p+31
    const int kp = wid & 1;             // split-K parity: ks = kp + 2*ki
    const int bx = blockIdx.x;          // 32 h-slices (16 cols each)
    const int jb = bx * 16;
    const int b0 = blockIdx.y * 128;    // batch base (4 groups)
    const int lq = lane >> 2;           // 0..7
    const int lr = (lane & 3) << 1;     // 0,2,4,6
    const int cid = blockIdx.y * 32 + bx;

    float* bsum = (float*)(smem + OFF_BSUM);

    unsigned gbase = 0;
    if (tid == 0) gbase = *(volatile unsigned*)&g_gen;

    // ---- prologue: zero h0 slice; convert x to permuted bf16 hi/lo ----
    for (int i = tid; i < 1024; i += NTHR) {
        size_t wi = (size_t)(b0 + (i >> 3)) * 256 + (size_t)bx * 8 + (i & 7);
        g_hhi[0][wi] = 0u; g_hlo[0][wi] = 0u;
    }
    for (size_t j = (size_t)cid * NTHR + tid; j < (size_t)BATCH * TLEN * IDIM / 4;
         j += (size_t)NCTA * NTHR) {
        float4 v = *(const float4*)(x + 4 * j);
        uint32_t hw[2], lw[2];
        split4(v, hw, lw);
        #pragma unroll
        for (int k = 0; k < 2; ++k) {
            size_t P = 2 * j + k;
            uint32_t d = (uint32_t)(P & 7);
            size_t widx = (P & ~(size_t)7) + 2u * (d & 3) + (d >> 2);
            g_xhi[widx] = hw[k];
            g_xlo[widx] = lw[k];
        }
    }

    float cst[8];
    #pragma unroll
    for (int j = 0; j < 8; ++j) cst[j] = 0.0f;

    gb_arrive(tid, gbase + 1);

    uint32_t bufA[16], bufB[16], lob[16];

    #pragma unroll 1
    for (int s = 0; s < 2 * TLEN; ++s) {
        const int dec = (s >= TLEN) ? 1 : 0;
        const int t = dec ? s - TLEN : s;
        const uint32_t* hhi = g_hhi[s & 1];
        const uint32_t* hlo = g_hlo[s & 1];

        // ---- per-phase weight + bias preload (hi/lo bf16, SW128) ----
        if (s == 0 || s == TLEN) {
            const float* Wih = dec ? dWih : eWih;
            const float* Whh = dec ? dWhh : eWhh;
            const float* bi  = dec ? dbih : ebih;
            const float* bh_ = dec ? dbhh : ebhh;
            __syncthreads();   // all warps done with previous-phase weights
            #pragma unroll 1
            for (int i = tid; i < 10240; i += NTHR) {   // 64 rows x 160 float4
                int rl = i / 160, k4 = i % 160;
                int c = k4 >> 4, kin = k4 & 15;
                int grow = (rl >> 4) * HDIM + jb + (rl & 15);
                const float* sp = (c < 2) ? (Wih + (size_t)grow * IDIM + c * 64 + kin * 4)
                                          : (Whh + (size_t)grow * HDIM + (c - 2) * 64 + kin * 4);
                float4 v = *(const float4*)sp;
                uint32_t off = (uint32_t)c * 8192u + SWZ((uint32_t)rl * 128u + (uint32_t)kin * 8u);
                cvt_sts(v, sb + OFF_WH + off, sb + OFF_WL + off);
            }
            if (tid < 64) {
                int g = tid >> 4, j = tid & 15;
                bsum[tid] = bi[g * HDIM + jb + j] + bh_[g * HDIM + jb + j];
            }
            __syncthreads();
        }

        float acc[2][8][4];
        #pragma unroll
        for (int fi = 0; fi < 2; ++fi)
            #pragma unroll
            for (int nt = 0; nt < 8; ++nt)
                #pragma unroll
                for (int q = 0; q < 4; ++q) acc[fi][nt][q] = 0.0f;

        auto pf_hi = [&](int c, uint32_t* buf) {
            #pragma unroll
            for (int ki = 0; ki < 2; ++ki) {
                const int ks = kp + 2 * ki;
                #pragma unroll
                for (int fi = 0; fi < 2; ++fi)
                    #pragma unroll
                    for (int rq = 0; rq < 2; ++rq) {
                        const int r = b0 + 32 * p + fi * 16 + lq + 8 * rq;
                        uint2 v;
                        if (c < 2)
                            v = ldcg_u2(g_xhi + ((size_t)r * TLEN + t) * 64
                                              + (size_t)(c * 32 + ks * 8 + lr));
                        else
                            v = ldcg_u2(hhi + (size_t)r * 256
                                            + (size_t)((c - 2) * 32 + ks * 8 + lr));
                        buf[ki * 8 + fi * 4 + rq]     = v.x;   // a0/a1 (k-lo)
                        buf[ki * 8 + fi * 4 + 2 + rq] = v.y;   // a2/a3 (k-hi)
                    }
            }
        };
        auto pf_lo = [&](int c, uint32_t* buf) {
            #pragma unroll
            for (int ki = 0; ki < 2; ++ki) {
                const int ks = kp + 2 * ki;
                #pragma unroll
                for (int fi = 0; fi < 2; ++fi)
                    #pragma unroll
                    for (int rq = 0; rq < 2; ++rq) {
                        const int r = b0 + 32 * p + fi * 16 + lq + 8 * rq;
                        uint2 v;
                        if (c < 2)
                            v = ldcg_u2(g_xlo + ((size_t)r * TLEN + t) * 64
                                              + (size_t)(c * 32 + ks * 8 + lr));
                        else
                            v = ldcg_u2(hlo + (size_t)r * 256
                                            + (size_t)((c - 2) * 32 + ks * 8 + lr));
                        buf[ki * 8 + fi * 4 + rq]     = v.x;
                        buf[ki * 8 + fi * 4 + 2 + rq] = v.y;
                    }
            }
        };
        auto body = [&](int c, const uint32_t* hib, const uint32_t* lo) {
            const uint32_t wb  = sb + OFF_WH + (uint32_t)c * 8192u;
            const uint32_t rbs = (uint32_t)(((lane & 16) ? 8 : 0) + (lane & 7));
            #pragma unroll
            for (int ki = 0; ki < 2; ++ki) {
                const int ks = kp + 2 * ki;
                const uint32_t kc = (uint32_t)(ks * 32 + ((lane & 8) ? 16 : 0));
                uint32_t bhf[16], blf[16];
                #pragma unroll
                for (int pp = 0; pp < 4; ++pp) {
                    uint32_t boff = SWZ(((uint32_t)(pp * 16) + rbs) * 128u + kc);
                    ldm4(bhf + 4 * pp, wb + boff);
                    ldm4(blf + 4 * pp, wb + 81920u + boff);
                }
                // pass-major: 16 independent accumulators between reuses
                #pragma unroll
                for (int fi = 0; fi < 2; ++fi)
                    #pragma unroll
                    for (int nt = 0; nt < 8; ++nt)
                        mma16816(acc[fi][nt], hib + ki * 8 + fi * 4, bhf + 2 * nt);
                #pragma unroll
                for (int fi = 0; fi < 2; ++fi)
                    #pragma unroll
                    for (int nt = 0; nt < 8; ++nt)
                        mma16816(acc[fi][nt], lo + ki * 8 + fi * 4, bhf + 2 * nt);
                #pragma unroll
                for (int fi = 0; fi < 2; ++fi)
                    #pragma unroll
                    for (int nt = 0; nt < 8; ++nt)
                        mma16816(acc[fi][nt], hib + ki * 8 + fi * 4, blf + 2 * nt);
            }
        };

        // x-chunks (h-independent) before the barrier wait
        pf_hi(0, bufA); pf_lo(0, lob); pf_hi(1, bufB);
        body(0, bufA, lob);
        pf_lo(1, lob);
        body(1, bufB, lob);
        gb_wait(tid, gbase + 1 + (unsigned)s);
        pf_hi(2, bufA);
        #pragma unroll 1
        for (int c = 2; c < 10; ++c) {
            uint32_t* cur = (c & 1) ? bufB : bufA;
            uint32_t* nxt = (c & 1) ? bufA : bufB;
            pf_lo(c, lob);
            if (c < 9) pf_hi(c + 1, nxt);
            body(c, cur, lob);
        }

        // ---- bidirectional split-K exchange: warp kp keeps half fi=kp ----
        const uint32_t send = sb + OFF_XCH + (uint32_t)p * 9216u + (uint32_t)(1 - kp) * 4608u;
        const uint32_t recv = sb + OFF_XCH + (uint32_t)p * 9216u + (uint32_t)kp * 4608u;
        {
            const int fiS = 1 - kp;
            #pragma unroll
            for (int nt = 0; nt < 8; ++nt)
                #pragma unroll
                for (int qr = 0; qr < 2; ++qr) {
                    uint32_t a = send + (uint32_t)(lq + 8 * qr) * 288u
                                      + (uint32_t)(nt * 8 + lr) * 4u;
                    asm volatile("st.shared.v2.f32 [%0], {%1,%2};" :: "r"(a),
                        "f"(acc[fiS][nt][2 * qr]), "f"(acc[fiS][nt][2 * qr + 1]) : "memory");
                }
        }
        __syncthreads();
        {
            #pragma unroll
            for (int nt = 0; nt < 8; ++nt)
                #pragma unroll
                for (int qr = 0; qr < 2; ++qr) {
                    uint32_t a = recv + (uint32_t)(lq + 8 * qr) * 288u
                                      + (uint32_t)(nt * 8 + lr) * 4u;
                    float px, py;
                    asm volatile("ld.shared.v2.f32 {%0,%1}, [%2];" : "=f"(px), "=f"(py) : "r"(a));
                    acc[kp][nt][2 * qr]     += px;
                    acc[kp][nt][2 * qr + 1] += py;
                }
        }

        // ---- fused gate epilogue: warp kp owns rows 32p + kp*16 ----
        {
            const int nb = (s + 1) & 1;
            #pragma unroll
            for (int qr = 0; qr < 2; ++qr) {
                const int r = b0 + 32 * p + kp * 16 + lq + 8 * qr;
                uint32_t hw[2], lw[2];
                #pragma unroll
                for (int nh = 0; nh < 2; ++nh) {
                    float hv[2];
                    #pragma unroll
                    for (int e = 0; e < 2; ++e) {
                        const int q = 2 * qr + e, j = nh * 8 + lr + e;
                        float pi  = acc[kp][nh][q]     + bsum[j];
                        float pf_ = acc[kp][2 + nh][q] + bsum[16 + j];
                        float pg  = acc[kp][4 + nh][q] + bsum[32 + j];
                        float po  = acc[kp][6 + nh][q] + bsum[48 + j];
                        float iv = sig_(pi), fv = sig_(pf_), gv = tnh_(pg), ov = sig_(po);
                        const int ci = qr * 4 + nh * 2 + e;
                        float cn = fv * cst[ci] + iv * gv;
                        cst[ci] = cn;
                        hv[e] = ov * tnh_(cn);
                    }
                    __nv_bfloat162 h2 = __floats2bfloat162_rn(hv[0], hv[1]);
                    __nv_bfloat162 l2 = __floats2bfloat162_rn(hv[0] - __bfloat162float(h2.x),
                                                              hv[1] - __bfloat162float(h2.y));
                    hw[nh] = *(uint32_t*)&h2;
                    lw[nh] = *(uint32_t*)&l2;
                }
                // permuted slots: word d = nh*4 + lr/2 -> slot lr + nh (adjacent pair)
                const size_t wi = (size_t)r * 256 + (size_t)bx * 8 + lr;
                *(uint2*)&g_hhi[nb][wi] = make_uint2(hw[0], hw[1]);
                *(uint2*)&g_hlo[nb][wi] = make_uint2(lw[0], lw[1]);
            }
        }
        __syncthreads();
        gb_arrive(tid, gbase + 2 + (unsigned)s);
    }

    // ---- fc epilogue: final h in buffer 0 (permuted layout) ----
    gb_wait(tid, gbase + 1 + 2 * TLEN);
    if (bx == 0) {
        for (int r = wid; r < 128; r += 8) {
            const size_t base = (size_t)(b0 + r) * 256;
            float ssum = 0.0f;
            for (int kk = lane; kk < 256; kk += 32) {
                uint32_t hwv = ldcg_u32(&g_hhi[0][base + kk]);
                uint32_t lwv = ldcg_u32(&g_hlo[0][base + kk]);
                int slot = kk & 7;
                int d = (slot & 1) * 4 + (slot >> 1);
                int J = ((kk & ~7) + d) * 2;
                __nv_bfloat162 h2 = *(__nv_bfloat162*)&hwv;
                __nv_bfloat162 l2 = *(__nv_bfloat162*)&lwv;
                ssum += (__bfloat162float(h2.x) + __bfloat162float(l2.x)) * fcW[J]
                      + (__bfloat162float(h2.y) + __bfloat162float(l2.y)) * fcW[J + 1];
            }
            #pragma unroll
            for (int o = 16; o; o >>= 1) ssum += __shfl_xor_sync(0xffffffffu, ssum, o);
            if (lane == 0) out[b0 + r] = ssum + fcb[0];
        }
    }
}

extern "C" void kernel_launch(void* const* d_in, const int* in_sizes, int n_in,
                              void* d_out, int out_size)
{
    (void)in_sizes; (void)n_in; (void)out_size;
    cudaFuncSetAttribute(lstm_mma6, cudaFuncAttributeMaxDynamicSharedMemorySize, SMEM_BYTES);
    dim3 grid(32, 4);   // 32 h-slices x 4 batch groups = 128 CTAs (1/SM)
    lstm_mma6<<<grid, NTHR, SMEM_BYTES>>>(
        (const float*)d_in[0],
        (const float*)d_in[1], (const float*)d_in[2],
        (const float*)d_in[3], (const float*)d_in[4],
        (const float*)d_in[5], (const float*)d_in[6],
        (const float*)d_in[7], (const float*)d_in[8],
        (const float*)d_in[9], (const float*)d_in[10],
        (float*)d_out);
}

// round 11
// speedup vs baseline: 1.4286x; 1.2328x over previous
#include <cuda_runtime.h>
#include <cuda_bf16.h>
#include <cstdint>

#define BATCH 512
#define TLEN  512
#define IDIM  128
#define HDIM  512
#define NCTA  128

#define OFF_BSUM  0
#define OFF_XCH   1024                    // 4 pairs * 2 halves * 4608B
#define OFF_WH    38912
#define OFF_WL    (OFF_WH + 81920)
#define SMEM_BYTES (OFF_WL + 81920)       // 202752

__device__ float    g_h[2][BATCH * HDIM];
__device__ unsigned g_count, g_gen;

__device__ __forceinline__ uint32_t smem_u32(const void* p) {
    uint32_t a;
    asm("{ .reg .u64 t; cvta.to.shared.u64 t, %1; cvt.u32.u64 %0, t; }" : "=r"(a) : "l"(p));
    return a;
}
#define SWZ(o) ((o) ^ (((o) >> 3) & 0x70))

__device__ __forceinline__ void ldm4(uint32_t* r, uint32_t addr) {
    asm volatile("ldmatrix.sync.aligned.m8n8.x4.shared.b16 {%0,%1,%2,%3}, [%4];"
        : "=r"(r[0]), "=r"(r[1]), "=r"(r[2]), "=r"(r[3]) : "r"(addr));
}
__device__ __forceinline__ void mma16816(float* d, const uint32_t* a, const uint32_t* b) {
    asm volatile("mma.sync.aligned.m16n8k16.row.col.f32.bf16.bf16.f32 "
        "{%0,%1,%2,%3},{%4,%5,%6,%7},{%8,%9},{%0,%1,%2,%3};"
        : "+f"(d[0]), "+f"(d[1]), "+f"(d[2]), "+f"(d[3])
        : "r"(a[0]), "r"(a[1]), "r"(a[2]), "r"(a[3]), "r"(b[0]), "r"(b[1]));
}

// ---- light grid barrier: acq_rel arrival + release/acquire generation ----
__device__ __forceinline__ void gb_arrive(int tid, unsigned target) {
    if (tid == 0) {
        unsigned old;
        asm volatile("atom.acq_rel.gpu.global.add.u32 %0, [%1], 1;"
                     : "=r"(old) : "l"(&g_count) : "memory");
        if (old == NCTA - 1) {
            asm volatile("st.relaxed.gpu.global.u32 [%0], %1;" :: "l"(&g_count), "r"(0u) : "memory");
            asm volatile("st.release.gpu.global.u32 [%0], %1;" :: "l"(&g_gen), "r"(target) : "memory");
        }
    }
}
__device__ __forceinline__ void gb_wait(int tid, unsigned target) {
    if (tid == 0) {
        unsigned g;
        do {
            asm volatile("ld.acquire.gpu.global.u32 %0, [%1];" : "=r"(g) : "l"(&g_gen) : "memory");
        } while ((int)(g - target) < 0);
    }
    __syncthreads();
}

// hi/lo bf16 split of a float4, stored as two 8-byte shared words (weights).
__device__ __forceinline__ void cvt_sts(float4 v, uint32_t ah, uint32_t al) {
    __nv_bfloat162 h0 = __floats2bfloat162_rn(v.x, v.y);
    __nv_bfloat162 h1 = __floats2bfloat162_rn(v.z, v.w);
    float lx = v.x - __bfloat162float(h0.x), ly = v.y - __bfloat162float(h0.y);
    float lz = v.z - __bfloat162float(h1.x), lw = v.w - __bfloat162float(h1.y);
    __nv_bfloat162 l0 = __floats2bfloat162_rn(lx, ly);
    __nv_bfloat162 l1 = __floats2bfloat162_rn(lz, lw);
    uint64_t hv = ((uint64_t)*(uint32_t*)&h1 << 32) | *(uint32_t*)&h0;
    uint64_t lv = ((uint64_t)*(uint32_t*)&l1 << 32) | *(uint32_t*)&l0;
    asm volatile("st.shared.b64 [%0], %1;" :: "r"(ah), "l"(hv) : "memory");
    asm volatile("st.shared.b64 [%0], %1;" :: "r"(al), "l"(lv) : "memory");
}

__device__ __forceinline__ float sig_(float x) { return 1.0f / (1.0f + __expf(-x)); }
__device__ __forceinline__ float tnh_(float x) { return 2.0f / (1.0f + __expf(-2.0f * x)) - 1.0f; }

__global__ void __launch_bounds__(256, 1) lstm_mma7(
    const float* __restrict__ x,
    const float* __restrict__ eWih, const float* __restrict__ eWhh,
    const float* __restrict__ ebih, const float* __restrict__ ebhh,
    const float* __restrict__ dWih, const float* __restrict__ dWhh,
    const float* __restrict__ dbih, const float* __restrict__ dbhh,
    const float* __restrict__ fcW,  const float* __restrict__ fcb,
    float* __restrict__ out)
{
    extern __shared__ __align__(1024) char smem[];
    const uint32_t sb = smem_u32(smem);
    const int tid = threadIdx.x, wid = tid >> 5, lane = tid & 31;
    const int p  = wid >> 1;            // pair/tile 0..3 -> rows 32p..32p+31
    const int kp = wid & 1;             // k-parity within pair
    const int jb = blockIdx.x * 16;     // h-col base
    const int b0 = blockIdx.y * 128;    // batch base
    const int lq = lane >> 2;           // 0..7
    const int lr = (lane & 3) << 1;     // 0,2,4,6

    float* bsum = (float*)(smem + OFF_BSUM);
    char*  xch  = smem + OFF_XCH + p * 9216;   // 32 rows x 72 f32 (288B stride)

    unsigned gbase = 0;
    if (tid == 0) gbase = *(volatile unsigned*)&g_gen;

    // zero this CTA's slice of h0
    for (int i = tid; i < 2048; i += 256) {
        int r = i >> 5, c = i & 31;
        g_h[0][(size_t)(b0 + r) * HDIM + jb + c] = 0.0f;
    }
    float cst[16];
    #pragma unroll
    for (int j = 0; j < 16; ++j) cst[j] = 0.0f;

    gb_arrive(tid, gbase + 1);
    gb_wait(tid, gbase + 1);

    float2 bufA[16], bufB[16];

    #pragma unroll 1
    for (int s = 0; s < 2 * TLEN; ++s) {
        const int dec = (s >= TLEN) ? 1 : 0;
        const int t = dec ? s - TLEN : s;
        const float* hin  = g_h[s & 1];
        float*       hout = g_h[(s + 1) & 1];

        // ---- per-phase weight + bias preload (hi/lo bf16 in SMEM) ----
        if (s == 0 || s == TLEN) {
            const float* Wih = dec ? dWih : eWih;
            const float* Whh = dec ? dWhh : eWhh;
            const float* bi  = dec ? dbih : ebih;
            const float* bh  = dec ? dbhh : ebhh;
            __syncthreads();
            #pragma unroll 1
            for (int i = tid; i < 10240; i += 256) {   // 64 rows x 160 float4
                int rl = i / 160, k4 = i % 160;
                int c = k4 >> 4, kin = k4 & 15;
                int grow = (rl >> 4) * HDIM + jb + (rl & 15);
                const float* sp = (c < 2) ? (Wih + (size_t)grow * IDIM + c * 64 + kin * 4)
                                          : (Whh + (size_t)grow * HDIM + (c - 2) * 64 + kin * 4);
                float4 v = *(const float4*)sp;
                uint32_t off = (uint32_t)c * 8192u + SWZ((uint32_t)rl * 128u + (uint32_t)kin * 8u);
                cvt_sts(v, sb + OFF_WH + off, sb + OFF_WL + off);
            }
            if (tid < 64) {
                int g = tid >> 4, j = tid & 15;
                bsum[tid] = bi[g * HDIM + jb + j] + bh[g * HDIM + jb + j];
            }
            __syncthreads();
        }

        float acc[2][8][4];
        #pragma unroll
        for (int fi = 0; fi < 2; ++fi)
            #pragma unroll
            for (int nt = 0; nt < 8; ++nt)
                #pragma unroll
                for (int q = 0; q < 4; ++q) acc[fi][nt][q] = 0.0f;

        // prefetch A fragments of chunk c (f32, exact MMA-fragment elements)
        auto pf = [&](int c, float2* buf) {
            const float* base; size_t rs;
            if (c < 2) { base = x + (size_t)b0 * TLEN * IDIM + (size_t)t * IDIM + c * 64; rs = (size_t)TLEN * IDIM; }
            else       { base = hin + (size_t)b0 * HDIM + (c - 2) * 64; rs = HDIM; }
            #pragma unroll
            for (int ki = 0; ki < 2; ++ki) {
                const int ks = kp + 2 * ki;
                #pragma unroll
                for (int fi = 0; fi < 2; ++fi)
                    #pragma unroll
                    for (int q = 0; q < 4; ++q) {
                        int r  = 32 * p + fi * 16 + lq + (q & 1) * 8;
                        int kk = ks * 16 + lr + (q >> 1) * 8;
                        buf[ki * 8 + fi * 4 + q] = __ldcg((const float2*)(base + (size_t)r * rs + kk));
                    }
            }
        };

        auto compute = [&](int c, const float2* buf) {
            const uint32_t wb = sb + OFF_WH + (uint32_t)c * 8192u;
            #pragma unroll
            for (int ki = 0; ki < 2; ++ki) {
                const int ks = kp + 2 * ki;
                uint32_t bh[16], bl[16];
                #pragma unroll
                for (int pp = 0; pp < 4; ++pp) {
                    uint32_t brow = (uint32_t)(pp * 16 + ((lane & 16) ? 8 : 0) + (lane & 7));
                    uint32_t boff = SWZ(brow * 128u + (uint32_t)ks * 32u + ((lane & 8) ? 16u : 0u));
                    ldm4(bh + 4 * pp, wb + boff);
                    ldm4(bl + 4 * pp, wb + 81920u + boff);
                }
                uint32_t ah[2][4], al[2][4];
                #pragma unroll
                for (int fi = 0; fi < 2; ++fi)
                    #pragma unroll
                    for (int q = 0; q < 4; ++q) {
                        float2 v = buf[ki * 8 + fi * 4 + q];
                        __nv_bfloat162 h2 = __floats2bfloat162_rn(v.x, v.y);
                        float rx = v.x - __bfloat162float(h2.x);
                        float ry = v.y - __bfloat162float(h2.y);
                        __nv_bfloat162 l2 = __floats2bfloat162_rn(rx, ry);
                        ah[fi][q] = *(uint32_t*)&h2;
                        al[fi][q] = *(uint32_t*)&l2;
                    }
                // pass-major: 16 independent accumulators between reuses
                #pragma unroll
                for (int fi = 0; fi < 2; ++fi)
                    #pragma unroll
                    for (int nt = 0; nt < 8; ++nt)
                        mma16816(acc[fi][nt], ah[fi], bh + 2 * nt);
                #pragma unroll
                for (int fi = 0; fi < 2; ++fi)
                    #pragma unroll
                    for (int nt = 0; nt < 8; ++nt)
                        mma16816(acc[fi][nt], al[fi], bh + 2 * nt);
                #pragma unroll
                for (int fi = 0; fi < 2; ++fi)
                    #pragma unroll
                    for (int nt = 0; nt < 8; ++nt)
                        mma16816(acc[fi][nt], ah[fi], bl + 2 * nt);
            }
        };

        // x-chunks (h-independent) run before the barrier wait -> overlap
        pf(0, bufA); pf(1, bufB);
        compute(0, bufA);
        compute(1, bufB);
        gb_wait(tid, gbase + 1 + (unsigned)s);   // h from step s-1 ready
        pf(2, bufA);
        #pragma unroll 1
        for (int c = 2; c < 10; ++c) {
            float2* cur = (c & 1) ? bufB : bufA;
            float2* nxt = (c & 1) ? bufA : bufB;
            if (c < 9) pf(c + 1, nxt);
            compute(c, cur);
        }

        // ---- split-K exchange + fused gate epilogue ----
        if (kp) {
            #pragma unroll
            for (int fi = 0; fi < 2; ++fi)
                #pragma unroll
                for (int nt = 0; nt < 8; ++nt)
                    #pragma unroll
                    for (int qr = 0; qr < 2; ++qr) {
                        uint32_t rowl = (uint32_t)(fi * 16 + lq + qr * 8);
                        uint32_t col  = (uint32_t)(nt * 8 + lr);
                        *(float2*)(xch + rowl * 288 + col * 4) =
                            make_float2(acc[fi][nt][2 * qr], acc[fi][nt][2 * qr + 1]);
                    }
        }
        __syncthreads();
        if (!kp) {
            #pragma unroll
            for (int fi = 0; fi < 2; ++fi)
                #pragma unroll
                for (int nt = 0; nt < 8; ++nt)
                    #pragma unroll
                    for (int qr = 0; qr < 2; ++qr) {
                        uint32_t rowl = (uint32_t)(fi * 16 + lq + qr * 8);
                        uint32_t col  = (uint32_t)(nt * 8 + lr);
                        float2 pv = *(const float2*)(xch + rowl * 288 + col * 4);
                        acc[fi][nt][2 * qr]     += pv.x;
                        acc[fi][nt][2 * qr + 1] += pv.y;
                    }
            #pragma unroll
            for (int fi = 0; fi < 2; ++fi)
                #pragma unroll
                for (int qr = 0; qr < 2; ++qr) {
                    const int r = 32 * p + fi * 16 + lq + qr * 8;
                    const int b = b0 + r;
                    float2 pi, pf_, pg, po;   // avoid aliasing with lambda
                    #pragma unroll
                    for (int nh = 0; nh < 2; ++nh) {
                        float hv[2];
                        #pragma unroll
                        for (int e = 0; e < 2; ++e) {
                            const int q = 2 * qr + e;
                            const int j = nh * 8 + lr + e;
                            float vi = acc[fi][nh][q]     + bsum[j];
                            float vf = acc[fi][2 + nh][q] + bsum[16 + j];
                            float vg = acc[fi][4 + nh][q] + bsum[32 + j];
                            float vo = acc[fi][6 + nh][q] + bsum[48 + j];
                            float iv = sig_(vi), fv = sig_(vf), gv = tnh_(vg), ov = sig_(vo);
                            const int ci = fi * 8 + qr * 4 + nh * 2 + e;
                            float cn = fv * cst[ci] + iv * gv;
                            cst[ci] = cn;
                            hv[e] = ov * tnh_(cn);
                        }
                        *(float2*)(hout + (size_t)b * HDIM + jb + nh * 8 + lr) =
                            make_float2(hv[0], hv[1]);
                    }
                    (void)pi; (void)pf_; (void)pg; (void)po;
                }
        }
        __syncthreads();
        gb_arrive(tid, gbase + 2 + (unsigned)s);
    }

    // ---- fc epilogue: final h is in g_h[0] ----
    gb_wait(tid, gbase + 1 + 2 * TLEN);
    if (blockIdx.x == 0) {
        for (int r = wid; r < 128; r += 8) {
            const float* hr = g_h[0] + (size_t)(b0 + r) * HDIM;
            float ssum = 0.0f;
            #pragma unroll 4
            for (int k = lane; k < HDIM; k += 32) ssum += __ldcg(hr + k) * fcW[k];
            #pragma unroll
            for (int o = 16; o; o >>= 1) ssum += __shfl_xor_sync(0xffffffffu, ssum, o);
            if (lane == 0) out[b0 + r] = ssum + fcb[0];
        }
    }
}

extern "C" void kernel_launch(void* const* d_in, const int* in_sizes, int n_in,
                              void* d_out, int out_size)
{
    (void)in_sizes; (void)n_in; (void)out_size;
    cudaFuncSetAttribute(lstm_mma7, cudaFuncAttributeMaxDynamicSharedMemorySize, SMEM_BYTES);
    dim3 grid(32, 4);   // 32 h-slices x 4 batch groups = 128 CTAs (1/SM)
    lstm_mma7<<<grid, 256, SMEM_BYTES>>>(
        (const float*)d_in[0],
        (const float*)d_in[1], (const float*)d_in[2],
        (const float*)d_in[3], (const float*)d_in[4],
        (const float*)d_in[5], (const float*)d_in[6],
        (const float*)d_in[7], (const float*)d_in[8],
        (const float*)d_in[9], (const float*)d_in[10],
        (float*)d_out);
}